// round 5
// baseline (speedup 1.0000x reference)
#include <cuda_runtime.h>
#include <math.h>
#include <stdint.h>

#define BB 4
#define TT 2048
#define DD 1024
#define HH 16
#define HD 64
#define MM (BB*TT)           // 8192
#define N3 (3*DD)            // 3072

// Scratch (device globals: allocation-guard-safe)
__device__ float g_q[BB*HH*TT*HD];   // [B,H,T,hd]
__device__ float g_k[BB*HH*TT*HD];
__device__ float g_v[BB*HH*TT*HD];
__device__ float g_y[MM*DD];         // [B,T,D] (tf32-rounded by attn epilogue)
__device__ float g_xr[MM*DD];        // tf32-rounded x
__device__ float g_war[DD*N3];       // tf32-rounded W_attn
__device__ float g_wpr[DD*DD];       // tf32-rounded W_proj

__device__ __forceinline__ float tf32r(float x) {
    uint32_t u;
    asm("cvt.rna.tf32.f32 %0, %1;" : "=r"(u) : "f"(x));
    return __uint_as_float(u);
}
__device__ __forceinline__ uint32_t f2b(float x) { return __float_as_uint(x); }

#define MMA_TF32(d, a, b) \
    asm volatile("mma.sync.aligned.m16n8k8.row.col.f32.tf32.tf32.f32 " \
        "{%0,%1,%2,%3}, {%4,%5,%6,%7}, {%8,%9}, {%0,%1,%2,%3};" \
        : "+f"((d)[0]), "+f"((d)[1]), "+f"((d)[2]), "+f"((d)[3]) \
        : "r"((a)[0]), "r"((a)[1]), "r"((a)[2]), "r"((a)[3]), \
          "r"((b)[0]), "r"((b)[1]))

// ---------------------------------------------------------------------------
// Elementwise tf32 RNE rounding pass (hoisted out of GEMM mainloop)
// ---------------------------------------------------------------------------
__global__ __launch_bounds__(256)
void round_tf32(const float4* __restrict__ src, float4* __restrict__ dst, int n4)
{
    int i = blockIdx.x * blockDim.x + threadIdx.x;
    const int stride = gridDim.x * blockDim.x;
    for (; i < n4; i += stride) {
        float4 v = src[i];
        v.x = tf32r(v.x); v.y = tf32r(v.y); v.z = tf32r(v.z); v.w = tf32r(v.w);
        dst[i] = v;
    }
}

// ---------------------------------------------------------------------------
// Tensor-core TF32 GEMM: C[M,N] = A[M,1024] * B[1024,N] + bias
// CTA 128(M)x256(N), 8 warps 2x4, warp tile 64x64, KSTAGE=8, double buffered.
// Inputs pre-rounded to tf32. 1.0 LDS.32 per MMA (was 1.5).
// MODE 0: scatter into g_q/g_k/g_v head layout. MODE 1: plain C.
// ---------------------------------------------------------------------------
template<int MODE, int NTOT>
__global__ __launch_bounds__(256)
void mma_gemm(const float* __restrict__ A, const float* __restrict__ B,
              const float* __restrict__ bias, float* __restrict__ C)
{
    __shared__ float As[2][8][136];   // [buf][k][m]  (transposed A tile)
    __shared__ float Bs[2][8][264];   // [buf][k][n]

    const int tid = threadIdx.x;
    const int lane = tid & 31;
    const int wid = tid >> 5;
    const int warp_m = wid >> 2;      // 0..1
    const int warp_n = wid & 3;       // 0..3
    const int g = lane >> 2;          // 0..7
    const int tg = lane & 3;          // 0..3
    const int bx = blockIdx.x, by = blockIdx.y;

    const float* Ag = A + (size_t)(by * 128) * 1024;
    const float* Bg = B + bx * 256;

    // global->smem mapping (per stage of K=8)
    const int am  = tid >> 1;             // 0..127
    const int akc = (tid & 1) << 2;       // 0,4
    const int bk  = tid >> 5;             // 0..7
    const int bnc = (tid & 31) << 3;      // 0..248

    float acc[4][8][4];
    #pragma unroll
    for (int i = 0; i < 4; i++)
        #pragma unroll
        for (int j = 0; j < 8; j++)
            #pragma unroll
            for (int r = 0; r < 4; r++) acc[i][j][r] = 0.0f;

    float4 ra  = *(const float4*)&Ag[(size_t)am * 1024 + akc];
    float4 rb0 = *(const float4*)&Bg[(size_t)bk * NTOT + bnc];
    float4 rb1 = *(const float4*)&Bg[(size_t)bk * NTOT + bnc + 4];

    for (int s = 0; s < 128; s++) {
        const int buf = s & 1;

        As[buf][akc + 0][am] = ra.x;
        As[buf][akc + 1][am] = ra.y;
        As[buf][akc + 2][am] = ra.z;
        As[buf][akc + 3][am] = ra.w;
        *(float4*)&Bs[buf][bk][bnc]     = rb0;
        *(float4*)&Bs[buf][bk][bnc + 4] = rb1;
        __syncthreads();

        if (s < 127) {
            const int kb = (s + 1) * 8;
            ra  = *(const float4*)&Ag[(size_t)am * 1024 + kb + akc];
            rb0 = *(const float4*)&Bg[(size_t)(kb + bk) * NTOT + bnc];
            rb1 = *(const float4*)&Bg[(size_t)(kb + bk) * NTOT + bnc + 4];
        }

        uint32_t af[4][4];
        #pragma unroll
        for (int mi = 0; mi < 4; mi++) {
            const int bm = warp_m * 64 + mi * 16;
            af[mi][0] = f2b(As[buf][tg][bm + g]);
            af[mi][1] = f2b(As[buf][tg][bm + g + 8]);
            af[mi][2] = f2b(As[buf][tg + 4][bm + g]);
            af[mi][3] = f2b(As[buf][tg + 4][bm + g + 8]);
        }
        uint32_t bf[8][2];
        #pragma unroll
        for (int ni = 0; ni < 8; ni++) {
            const int bn = warp_n * 64 + ni * 8;
            bf[ni][0] = f2b(Bs[buf][tg][bn + g]);
            bf[ni][1] = f2b(Bs[buf][tg + 4][bn + g]);
        }
        #pragma unroll
        for (int mi = 0; mi < 4; mi++)
            #pragma unroll
            for (int ni = 0; ni < 8; ni++)
                MMA_TF32(acc[mi][ni], af[mi], bf[ni]);
    }

    // epilogue
    #pragma unroll
    for (int mi = 0; mi < 4; mi++) {
        #pragma unroll
        for (int ni = 0; ni < 8; ni++) {
            const int n = bx * 256 + warp_n * 64 + ni * 8 + 2 * tg;
            const float b0 = bias[n], b1 = bias[n + 1];
            #pragma unroll
            for (int p = 0; p < 2; p++) {
                const int m = by * 128 + warp_m * 64 + mi * 16 + g + p * 8;
                float2 v;
                v.x = acc[mi][ni][2 * p + 0] + b0;
                v.y = acc[mi][ni][2 * p + 1] + b1;
                if (MODE == 0) {
                    const int b_ = m >> 11;
                    const int t_ = m & 2047;
                    const int sel = n >> 10;
                    const int d = n & 1023;
                    float* dst = (sel == 0) ? g_q : ((sel == 1) ? g_k : g_v);
                    *(float2*)&dst[((size_t)(b_ * 16 + (d >> 6)) * 2048 + t_) * 64 + (d & 63)] = v;
                } else {
                    *(float2*)&C[(size_t)m * NTOT + n] = v;
                }
            }
        }
    }
}

// ---------------------------------------------------------------------------
// Tensor-core flash attention (causal, tf32 mma). Unchanged from R4 except
// the epilogue writes tf32-rounded y (proj input needs no further rounding).
// ---------------------------------------------------------------------------
#define ASTR 68
#define SMEM_ATTN ((2 * 64 * ASTR + 8 * 16 * ASTR) * 4)   // 69632 B

__global__ __launch_bounds__(256)
void attn_tc()
{
    extern __shared__ float smf[];
    float* Ks = smf;                        // [64][68]
    float* Vs = smf + 64 * ASTR;            // [64][68]
    float* Ps = smf + 2 * 64 * ASTR;        // [8][16][68]

    const int tid  = threadIdx.x;
    const int lane = tid & 31;
    const int wid  = tid >> 5;
    const int g    = lane >> 2;
    const int tg   = lane & 3;
    const int qt = blockIdx.x;
    const int h  = blockIdx.y;
    const int b  = blockIdx.z;

    const float* qb = g_q + (size_t)(b * HH + h) * TT * HD;
    const float* kb = g_k + (size_t)(b * HH + h) * TT * HD;
    const float* vb = g_v + (size_t)(b * HH + h) * TT * HD;

    float* Pw = Ps + wid * 16 * ASTR;

    uint32_t Qf[8][4];
    {
        const int r = lane >> 1;
        const int c = (lane & 1) * 32;
        const float* qrow = qb + (size_t)(qt * 128 + wid * 16 + r) * 64 + c;
        #pragma unroll
        for (int i = 0; i < 8; i++) {
            float4 v = *(const float4*)&qrow[i * 4];
            v.x = tf32r(v.x); v.y = tf32r(v.y); v.z = tf32r(v.z); v.w = tf32r(v.w);
            *(float4*)&Pw[r * ASTR + c + i * 4] = v;
        }
        __syncwarp();
        #pragma unroll
        for (int ks = 0; ks < 8; ks++) {
            Qf[ks][0] = f2b(Pw[g * ASTR + ks * 8 + tg]);
            Qf[ks][1] = f2b(Pw[(g + 8) * ASTR + ks * 8 + tg]);
            Qf[ks][2] = f2b(Pw[g * ASTR + ks * 8 + tg + 4]);
            Qf[ks][3] = f2b(Pw[(g + 8) * ASTR + ks * 8 + tg + 4]);
        }
    }

    float O[8][4];
    #pragma unroll
    for (int ni = 0; ni < 8; ni++)
        #pragma unroll
        for (int r = 0; r < 4; r++) O[ni][r] = 0.0f;
    float mi0 = -INFINITY, mi1 = -INFINITY, li0 = 0.0f, li1 = 0.0f;

    const int row0 = qt * 128 + wid * 16 + g;
    const int row1 = row0 + 8;
    const int wrow_min = qt * 128 + wid * 16;
    const float scale = 0.125f;
    const int nkt = 2 * qt + 2;

    for (int kt = 0; kt < nkt; kt++) {
        __syncthreads();
        {
            const int r = tid >> 2;
            const int c = (tid & 3) << 4;
            const float* krow = kb + (size_t)(kt * 64 + r) * 64 + c;
            const float* vrow = vb + (size_t)(kt * 64 + r) * 64 + c;
            #pragma unroll
            for (int i = 0; i < 4; i++) {
                float4 kv = *(const float4*)&krow[i * 4];
                kv.x = tf32r(kv.x); kv.y = tf32r(kv.y); kv.z = tf32r(kv.z); kv.w = tf32r(kv.w);
                *(float4*)&Ks[r * ASTR + c + i * 4] = kv;
                float4 vv = *(const float4*)&vrow[i * 4];
                vv.x = tf32r(vv.x); vv.y = tf32r(vv.y); vv.z = tf32r(vv.z); vv.w = tf32r(vv.w);
                *(float4*)&Vs[r * ASTR + c + i * 4] = vv;
            }
        }
        __syncthreads();

        float S[8][4];
        #pragma unroll
        for (int ni = 0; ni < 8; ni++)
            #pragma unroll
            for (int r = 0; r < 4; r++) S[ni][r] = 0.0f;

        #pragma unroll
        for (int ks = 0; ks < 8; ks++) {
            uint32_t bf[8][2];
            #pragma unroll
            for (int ni = 0; ni < 8; ni++) {
                bf[ni][0] = f2b(Ks[(ni * 8 + g) * ASTR + ks * 8 + tg]);
                bf[ni][1] = f2b(Ks[(ni * 8 + g) * ASTR + ks * 8 + tg + 4]);
            }
            #pragma unroll
            for (int ni = 0; ni < 8; ni++)
                MMA_TF32(S[ni], Qf[ks], bf[ni]);
        }

        if (kt * 64 + 63 > wrow_min) {
            #pragma unroll
            for (int ni = 0; ni < 8; ni++) {
                const int c0 = kt * 64 + ni * 8 + 2 * tg;
                S[ni][0] = (c0     > row0) ? -INFINITY : S[ni][0] * scale;
                S[ni][1] = (c0 + 1 > row0) ? -INFINITY : S[ni][1] * scale;
                S[ni][2] = (c0     > row1) ? -INFINITY : S[ni][2] * scale;
                S[ni][3] = (c0 + 1 > row1) ? -INFINITY : S[ni][3] * scale;
            }
        } else {
            #pragma unroll
            for (int ni = 0; ni < 8; ni++) {
                S[ni][0] *= scale; S[ni][1] *= scale;
                S[ni][2] *= scale; S[ni][3] *= scale;
            }
        }

        float m0 = -INFINITY, m1 = -INFINITY;
        #pragma unroll
        for (int ni = 0; ni < 8; ni++) {
            m0 = fmaxf(m0, fmaxf(S[ni][0], S[ni][1]));
            m1 = fmaxf(m1, fmaxf(S[ni][2], S[ni][3]));
        }
        m0 = fmaxf(m0, __shfl_xor_sync(0xffffffffu, m0, 1));
        m0 = fmaxf(m0, __shfl_xor_sync(0xffffffffu, m0, 2));
        m1 = fmaxf(m1, __shfl_xor_sync(0xffffffffu, m1, 1));
        m1 = fmaxf(m1, __shfl_xor_sync(0xffffffffu, m1, 2));
        const float mn0 = fmaxf(mi0, m0);
        const float mn1 = fmaxf(mi1, m1);
        const float a0 = __expf(mi0 - mn0);
        const float a1 = __expf(mi1 - mn1);
        mi0 = mn0; mi1 = mn1;

        float rs0 = 0.0f, rs1 = 0.0f;
        #pragma unroll
        for (int ni = 0; ni < 8; ni++) {
            const float p00 = __expf(S[ni][0] - mn0);
            const float p01 = __expf(S[ni][1] - mn0);
            const float p10 = __expf(S[ni][2] - mn1);
            const float p11 = __expf(S[ni][3] - mn1);
            rs0 += p00 + p01;
            rs1 += p10 + p11;
            float2 t0; t0.x = tf32r(p00); t0.y = tf32r(p01);
            *(float2*)&Pw[g * ASTR + ni * 8 + 2 * tg] = t0;
            float2 t1; t1.x = tf32r(p10); t1.y = tf32r(p11);
            *(float2*)&Pw[(g + 8) * ASTR + ni * 8 + 2 * tg] = t1;
            O[ni][0] *= a0; O[ni][1] *= a0;
            O[ni][2] *= a1; O[ni][3] *= a1;
        }
        rs0 += __shfl_xor_sync(0xffffffffu, rs0, 1);
        rs0 += __shfl_xor_sync(0xffffffffu, rs0, 2);
        rs1 += __shfl_xor_sync(0xffffffffu, rs1, 1);
        rs1 += __shfl_xor_sync(0xffffffffu, rs1, 2);
        li0 = li0 * a0 + rs0;
        li1 = li1 * a1 + rs1;
        __syncwarp();

        #pragma unroll
        for (int ks = 0; ks < 8; ks++) {
            uint32_t af[4];
            af[0] = f2b(Pw[g * ASTR + ks * 8 + tg]);
            af[1] = f2b(Pw[(g + 8) * ASTR + ks * 8 + tg]);
            af[2] = f2b(Pw[g * ASTR + ks * 8 + tg + 4]);
            af[3] = f2b(Pw[(g + 8) * ASTR + ks * 8 + tg + 4]);
            uint32_t bf[8][2];
            #pragma unroll
            for (int ni = 0; ni < 8; ni++) {
                bf[ni][0] = f2b(Vs[(ks * 8 + tg) * ASTR + ni * 8 + g]);
                bf[ni][1] = f2b(Vs[(ks * 8 + tg + 4) * ASTR + ni * 8 + g]);
            }
            #pragma unroll
            for (int ni = 0; ni < 8; ni++)
                MMA_TF32(O[ni], af, bf[ni]);
        }
    }

    const float inv0 = 1.0f / li0;
    const float inv1 = 1.0f / li1;
    float* y0 = g_y + (size_t)(b * TT + row0) * DD + h * HD;
    float* y1 = g_y + (size_t)(b * TT + row1) * DD + h * HD;
    #pragma unroll
    for (int ni = 0; ni < 8; ni++) {
        const int c = ni * 8 + 2 * tg;
        float2 v0; v0.x = tf32r(O[ni][0] * inv0); v0.y = tf32r(O[ni][1] * inv0);
        *(float2*)&y0[c] = v0;
        float2 v1; v1.x = tf32r(O[ni][2] * inv1); v1.y = tf32r(O[ni][3] * inv1);
        *(float2*)&y1[c] = v1;
    }
}

// ---------------------------------------------------------------------------
extern "C" void kernel_launch(void* const* d_in, const int* in_sizes, int n_in,
                              void* d_out, int out_size)
{
    (void)in_sizes; (void)n_in; (void)out_size;
    const float* x      = (const float*)d_in[0];
    const float* W_attn = (const float*)d_in[1];
    const float* b_attn = (const float*)d_in[2];
    const float* W_proj = (const float*)d_in[3];
    const float* b_proj = (const float*)d_in[4];
    float* out = (float*)d_out;

    float *xr = nullptr, *war = nullptr, *wpr = nullptr, *gy = nullptr;
    cudaGetSymbolAddress((void**)&xr, g_xr);
    cudaGetSymbolAddress((void**)&war, g_war);
    cudaGetSymbolAddress((void**)&wpr, g_wpr);
    cudaGetSymbolAddress((void**)&gy, g_y);

    static bool attr_done = false;
    if (!attr_done) {
        cudaFuncSetAttribute(attn_tc, cudaFuncAttributeMaxDynamicSharedMemorySize, SMEM_ATTN);
        attr_done = true;
    }

    // 0) pre-round inputs to tf32 (RNE)
    round_tf32<<<592, 256>>>((const float4*)x, (float4*)xr, MM * DD / 4);
    round_tf32<<<592, 256>>>((const float4*)W_attn, (float4*)war, DD * N3 / 4);
    round_tf32<<<592, 256>>>((const float4*)W_proj, (float4*)wpr, DD * DD / 4);

    // 1) QKV projection + head-layout scatter
    mma_gemm<0, N3><<<dim3(N3 / 256, MM / 128), 256>>>(xr, war, b_attn, nullptr);

    // 2) causal flash attention (writes tf32-rounded y)
    attn_tc<<<dim3(TT / 128, HH, BB), 256, SMEM_ATTN>>>();

    // 3) output projection
    mma_gemm<1, DD><<<dim3(DD / 256, MM / 128), 256>>>(gy, wpr, b_proj, out);
}

// round 6
// speedup vs baseline: 1.5197x; 1.5197x over previous
#include <cuda_runtime.h>
#include <math.h>
#include <stdint.h>

#define BB 4
#define TT 2048
#define DD 1024
#define HH 16
#define HD 64
#define MM (BB*TT)           // 8192
#define N3 (3*DD)            // 3072

// Scratch (device globals: allocation-guard-safe)
__device__ float g_q[BB*HH*TT*HD];   // [B,H,T,hd]  (tf32-rounded)
__device__ float g_k[BB*HH*TT*HD];
__device__ float g_v[BB*HH*TT*HD];
__device__ float g_y[MM*DD];         // [B,T,D]     (tf32-rounded)
__device__ float g_xr[MM*DD];        // tf32-rounded x
__device__ float g_war[DD*N3];       // tf32-rounded W_attn
__device__ float g_wpr[DD*DD];       // tf32-rounded W_proj

__device__ __forceinline__ float tf32r(float x) {
    uint32_t u;
    asm("cvt.rna.tf32.f32 %0, %1;" : "=r"(u) : "f"(x));
    return __uint_as_float(u);
}
__device__ __forceinline__ uint32_t f2b(float x) { return __float_as_uint(x); }

#define MMA_TF32(d, a, b) \
    asm volatile("mma.sync.aligned.m16n8k8.row.col.f32.tf32.tf32.f32 " \
        "{%0,%1,%2,%3}, {%4,%5,%6,%7}, {%8,%9}, {%0,%1,%2,%3};" \
        : "+f"((d)[0]), "+f"((d)[1]), "+f"((d)[2]), "+f"((d)[3]) \
        : "r"((a)[0]), "r"((a)[1]), "r"((a)[2]), "r"((a)[3]), \
          "r"((b)[0]), "r"((b)[1]))

// ---------------------------------------------------------------------------
// Elementwise tf32 RNE rounding pass (hoisted out of all mainloops)
// ---------------------------------------------------------------------------
__global__ __launch_bounds__(256)
void round_tf32(const float4* __restrict__ src, float4* __restrict__ dst, int n4)
{
    int i = blockIdx.x * blockDim.x + threadIdx.x;
    const int stride = gridDim.x * blockDim.x;
    for (; i < n4; i += stride) {
        float4 v = src[i];
        v.x = tf32r(v.x); v.y = tf32r(v.y); v.z = tf32r(v.z); v.w = tf32r(v.w);
        dst[i] = v;
    }
}

// ---------------------------------------------------------------------------
// Tensor-core TF32 GEMM (R4-proven geometry): C[M,N] = A[M,1024]*B[1024,N]+bias
// CTA 128x128, 8 warps (2M x 4N), warp tile 64x32, KSTAGE=16, double buffered.
// Inputs pre-rounded to tf32 -> NO CVTs in mainloop.
// MODE 0: scatter tf32-rounded q/k/v. MODE 1: plain fp32 C.
// ---------------------------------------------------------------------------
#define KSTAGE 16
#define SSTRIDE 136
#define BUFSZ (KSTAGE * SSTRIDE)
#define SMEM_GEMM (4 * BUFSZ * 4)

template<int MODE, int NTOT>
__global__ __launch_bounds__(256)
void mma_gemm(const float* __restrict__ A, const float* __restrict__ B,
              const float* __restrict__ bias, float* __restrict__ C)
{
    extern __shared__ float sm[];
    float* As = sm;
    float* Bs = sm + 2 * BUFSZ;

    const int tid = threadIdx.x;
    const int lane = tid & 31;
    const int wid = tid >> 5;
    const int warp_m = wid >> 2;
    const int warp_n = wid & 3;
    const int g = lane >> 2;
    const int tg = lane & 3;
    const int bx = blockIdx.x, by = blockIdx.y;

    const float* Ag = A + (size_t)(by * 128) * 1024;
    const float* Bg = B + bx * 128;

    const int am0 = tid >> 2;
    const int am1 = am0 + 64;
    const int akc = (tid & 3) << 2;
    const int bk0 = tid >> 5;
    const int bk1 = bk0 + 8;
    const int bnc = (tid & 31) << 2;

    float acc[4][4][4];
    #pragma unroll
    for (int i = 0; i < 4; i++)
        #pragma unroll
        for (int j = 0; j < 4; j++)
            #pragma unroll
            for (int r = 0; r < 4; r++) acc[i][j][r] = 0.0f;

    float4 ra0 = *(const float4*)&Ag[(size_t)am0 * 1024 + akc];
    float4 ra1 = *(const float4*)&Ag[(size_t)am1 * 1024 + akc];
    float4 rb0 = *(const float4*)&Bg[(size_t)bk0 * NTOT + bnc];
    float4 rb1 = *(const float4*)&Bg[(size_t)bk1 * NTOT + bnc];

    for (int s = 0; s < 1024 / KSTAGE; s++) {
        const int buf = s & 1;
        float* Ab = As + buf * BUFSZ;
        float* Bb = Bs + buf * BUFSZ;

        Ab[(akc + 0) * SSTRIDE + am0] = ra0.x;
        Ab[(akc + 1) * SSTRIDE + am0] = ra0.y;
        Ab[(akc + 2) * SSTRIDE + am0] = ra0.z;
        Ab[(akc + 3) * SSTRIDE + am0] = ra0.w;
        Ab[(akc + 0) * SSTRIDE + am1] = ra1.x;
        Ab[(akc + 1) * SSTRIDE + am1] = ra1.y;
        Ab[(akc + 2) * SSTRIDE + am1] = ra1.z;
        Ab[(akc + 3) * SSTRIDE + am1] = ra1.w;
        *(float4*)&Bb[bk0 * SSTRIDE + bnc] = rb0;
        *(float4*)&Bb[bk1 * SSTRIDE + bnc] = rb1;
        __syncthreads();

        if (s < 1024 / KSTAGE - 1) {
            const int kb = (s + 1) * KSTAGE;
            ra0 = *(const float4*)&Ag[(size_t)am0 * 1024 + kb + akc];
            ra1 = *(const float4*)&Ag[(size_t)am1 * 1024 + kb + akc];
            rb0 = *(const float4*)&Bg[(size_t)(kb + bk0) * NTOT + bnc];
            rb1 = *(const float4*)&Bg[(size_t)(kb + bk1) * NTOT + bnc];
        }

        #pragma unroll
        for (int ks = 0; ks < 2; ks++) {
            const int k8 = ks * 8;
            uint32_t af[4][4];
            #pragma unroll
            for (int mi = 0; mi < 4; mi++) {
                const int bm = warp_m * 64 + mi * 16;
                af[mi][0] = f2b(Ab[(k8 + tg) * SSTRIDE + bm + g]);
                af[mi][1] = f2b(Ab[(k8 + tg) * SSTRIDE + bm + g + 8]);
                af[mi][2] = f2b(Ab[(k8 + tg + 4) * SSTRIDE + bm + g]);
                af[mi][3] = f2b(Ab[(k8 + tg + 4) * SSTRIDE + bm + g + 8]);
            }
            uint32_t bf[4][2];
            #pragma unroll
            for (int ni = 0; ni < 4; ni++) {
                const int bn = warp_n * 32 + ni * 8;
                bf[ni][0] = f2b(Bb[(k8 + tg) * SSTRIDE + bn + g]);
                bf[ni][1] = f2b(Bb[(k8 + tg + 4) * SSTRIDE + bn + g]);
            }
            #pragma unroll
            for (int mi = 0; mi < 4; mi++)
                #pragma unroll
                for (int ni = 0; ni < 4; ni++)
                    MMA_TF32(acc[mi][ni], af[mi], bf[ni]);
        }
    }

    #pragma unroll
    for (int mi = 0; mi < 4; mi++) {
        #pragma unroll
        for (int ni = 0; ni < 4; ni++) {
            const int n = bx * 128 + warp_n * 32 + ni * 8 + 2 * tg;
            const float b0 = bias[n], b1 = bias[n + 1];
            #pragma unroll
            for (int p = 0; p < 2; p++) {
                const int row = warp_m * 64 + mi * 16 + g + p * 8;
                const int m = by * 128 + row;
                float2 v;
                if (MODE == 0) {
                    // round q/k/v here so attention needs no CVTs
                    v.x = tf32r(acc[mi][ni][2 * p + 0] + b0);
                    v.y = tf32r(acc[mi][ni][2 * p + 1] + b1);
                    const int b_ = m >> 11;
                    const int t_ = m & 2047;
                    const int sel = n >> 10;
                    const int d = n & 1023;
                    float* dst = (sel == 0) ? g_q : ((sel == 1) ? g_k : g_v);
                    *(float2*)&dst[((size_t)(b_ * 16 + (d >> 6)) * 2048 + t_) * 64 + (d & 63)] = v;
                } else {
                    v.x = acc[mi][ni][2 * p + 0] + b0;
                    v.y = acc[mi][ni][2 * p + 1] + b1;
                    *(float2*)&C[(size_t)m * NTOT + n] = v;
                }
            }
        }
    }
}

// ---------------------------------------------------------------------------
// Tensor-core flash attention (causal, tf32 mma). q/k/v pre-rounded ->
// no CVTs in staging or Q load; P rounded online; y rounded at epilogue.
// ---------------------------------------------------------------------------
#define ASTR 68
#define SMEM_ATTN ((2 * 64 * ASTR + 8 * 16 * ASTR) * 4)   // 69632 B

__global__ __launch_bounds__(256)
void attn_tc()
{
    extern __shared__ float smf[];
    float* Ks = smf;                        // [64][68]
    float* Vs = smf + 64 * ASTR;            // [64][68]
    float* Ps = smf + 2 * 64 * ASTR;        // [8][16][68]

    const int tid  = threadIdx.x;
    const int lane = tid & 31;
    const int wid  = tid >> 5;
    const int g    = lane >> 2;
    const int tg   = lane & 3;
    const int qt = blockIdx.x;
    const int h  = blockIdx.y;
    const int b  = blockIdx.z;

    const float* qb = g_q + (size_t)(b * HH + h) * TT * HD;
    const float* kb = g_k + (size_t)(b * HH + h) * TT * HD;
    const float* vb = g_v + (size_t)(b * HH + h) * TT * HD;

    float* Pw = Ps + wid * 16 * ASTR;

    uint32_t Qf[8][4];
    {
        const int r = lane >> 1;
        const int c = (lane & 1) * 32;
        const float* qrow = qb + (size_t)(qt * 128 + wid * 16 + r) * 64 + c;
        #pragma unroll
        for (int i = 0; i < 8; i++)
            *(float4*)&Pw[r * ASTR + c + i * 4] = *(const float4*)&qrow[i * 4];
        __syncwarp();
        #pragma unroll
        for (int ks = 0; ks < 8; ks++) {
            Qf[ks][0] = f2b(Pw[g * ASTR + ks * 8 + tg]);
            Qf[ks][1] = f2b(Pw[(g + 8) * ASTR + ks * 8 + tg]);
            Qf[ks][2] = f2b(Pw[g * ASTR + ks * 8 + tg + 4]);
            Qf[ks][3] = f2b(Pw[(g + 8) * ASTR + ks * 8 + tg + 4]);
        }
    }

    float O[8][4];
    #pragma unroll
    for (int ni = 0; ni < 8; ni++)
        #pragma unroll
        for (int r = 0; r < 4; r++) O[ni][r] = 0.0f;
    float mi0 = -INFINITY, mi1 = -INFINITY, li0 = 0.0f, li1 = 0.0f;

    const int row0 = qt * 128 + wid * 16 + g;
    const int row1 = row0 + 8;
    const int wrow_min = qt * 128 + wid * 16;
    const float scale = 0.125f;
    const int nkt = 2 * qt + 2;

    for (int kt = 0; kt < nkt; kt++) {
        __syncthreads();
        {
            const int r = tid >> 2;
            const int c = (tid & 3) << 4;
            const float* krow = kb + (size_t)(kt * 64 + r) * 64 + c;
            const float* vrow = vb + (size_t)(kt * 64 + r) * 64 + c;
            #pragma unroll
            for (int i = 0; i < 4; i++) {
                *(float4*)&Ks[r * ASTR + c + i * 4] = *(const float4*)&krow[i * 4];
                *(float4*)&Vs[r * ASTR + c + i * 4] = *(const float4*)&vrow[i * 4];
            }
        }
        __syncthreads();

        float S[8][4];
        #pragma unroll
        for (int ni = 0; ni < 8; ni++)
            #pragma unroll
            for (int r = 0; r < 4; r++) S[ni][r] = 0.0f;

        #pragma unroll
        for (int ks = 0; ks < 8; ks++) {
            uint32_t bf[8][2];
            #pragma unroll
            for (int ni = 0; ni < 8; ni++) {
                bf[ni][0] = f2b(Ks[(ni * 8 + g) * ASTR + ks * 8 + tg]);
                bf[ni][1] = f2b(Ks[(ni * 8 + g) * ASTR + ks * 8 + tg + 4]);
            }
            #pragma unroll
            for (int ni = 0; ni < 8; ni++)
                MMA_TF32(S[ni], Qf[ks], bf[ni]);
        }

        if (kt * 64 + 63 > wrow_min) {
            #pragma unroll
            for (int ni = 0; ni < 8; ni++) {
                const int c0 = kt * 64 + ni * 8 + 2 * tg;
                S[ni][0] = (c0     > row0) ? -INFINITY : S[ni][0] * scale;
                S[ni][1] = (c0 + 1 > row0) ? -INFINITY : S[ni][1] * scale;
                S[ni][2] = (c0     > row1) ? -INFINITY : S[ni][2] * scale;
                S[ni][3] = (c0 + 1 > row1) ? -INFINITY : S[ni][3] * scale;
            }
        } else {
            #pragma unroll
            for (int ni = 0; ni < 8; ni++) {
                S[ni][0] *= scale; S[ni][1] *= scale;
                S[ni][2] *= scale; S[ni][3] *= scale;
            }
        }

        float m0 = -INFINITY, m1 = -INFINITY;
        #pragma unroll
        for (int ni = 0; ni < 8; ni++) {
            m0 = fmaxf(m0, fmaxf(S[ni][0], S[ni][1]));
            m1 = fmaxf(m1, fmaxf(S[ni][2], S[ni][3]));
        }
        m0 = fmaxf(m0, __shfl_xor_sync(0xffffffffu, m0, 1));
        m0 = fmaxf(m0, __shfl_xor_sync(0xffffffffu, m0, 2));
        m1 = fmaxf(m1, __shfl_xor_sync(0xffffffffu, m1, 1));
        m1 = fmaxf(m1, __shfl_xor_sync(0xffffffffu, m1, 2));
        const float mn0 = fmaxf(mi0, m0);
        const float mn1 = fmaxf(mi1, m1);
        const float a0 = __expf(mi0 - mn0);
        const float a1 = __expf(mi1 - mn1);
        mi0 = mn0; mi1 = mn1;

        float rs0 = 0.0f, rs1 = 0.0f;
        #pragma unroll
        for (int ni = 0; ni < 8; ni++) {
            const float p00 = __expf(S[ni][0] - mn0);
            const float p01 = __expf(S[ni][1] - mn0);
            const float p10 = __expf(S[ni][2] - mn1);
            const float p11 = __expf(S[ni][3] - mn1);
            rs0 += p00 + p01;
            rs1 += p10 + p11;
            float2 t0; t0.x = tf32r(p00); t0.y = tf32r(p01);
            *(float2*)&Pw[g * ASTR + ni * 8 + 2 * tg] = t0;
            float2 t1; t1.x = tf32r(p10); t1.y = tf32r(p11);
            *(float2*)&Pw[(g + 8) * ASTR + ni * 8 + 2 * tg] = t1;
            O[ni][0] *= a0; O[ni][1] *= a0;
            O[ni][2] *= a1; O[ni][3] *= a1;
        }
        rs0 += __shfl_xor_sync(0xffffffffu, rs0, 1);
        rs0 += __shfl_xor_sync(0xffffffffu, rs0, 2);
        rs1 += __shfl_xor_sync(0xffffffffu, rs1, 1);
        rs1 += __shfl_xor_sync(0xffffffffu, rs1, 2);
        li0 = li0 * a0 + rs0;
        li1 = li1 * a1 + rs1;
        __syncwarp();

        #pragma unroll
        for (int ks = 0; ks < 8; ks++) {
            uint32_t af[4];
            af[0] = f2b(Pw[g * ASTR + ks * 8 + tg]);
            af[1] = f2b(Pw[(g + 8) * ASTR + ks * 8 + tg]);
            af[2] = f2b(Pw[g * ASTR + ks * 8 + tg + 4]);
            af[3] = f2b(Pw[(g + 8) * ASTR + ks * 8 + tg + 4]);
            uint32_t bf[8][2];
            #pragma unroll
            for (int ni = 0; ni < 8; ni++) {
                bf[ni][0] = f2b(Vs[(ks * 8 + tg) * ASTR + ni * 8 + g]);
                bf[ni][1] = f2b(Vs[(ks * 8 + tg + 4) * ASTR + ni * 8 + g]);
            }
            #pragma unroll
            for (int ni = 0; ni < 8; ni++)
                MMA_TF32(O[ni], af, bf[ni]);
        }
    }

    const float inv0 = 1.0f / li0;
    const float inv1 = 1.0f / li1;
    float* y0 = g_y + (size_t)(b * TT + row0) * DD + h * HD;
    float* y1 = g_y + (size_t)(b * TT + row1) * DD + h * HD;
    #pragma unroll
    for (int ni = 0; ni < 8; ni++) {
        const int c = ni * 8 + 2 * tg;
        float2 v0; v0.x = tf32r(O[ni][0] * inv0); v0.y = tf32r(O[ni][1] * inv0);
        *(float2*)&y0[c] = v0;
        float2 v1; v1.x = tf32r(O[ni][2] * inv1); v1.y = tf32r(O[ni][3] * inv1);
        *(float2*)&y1[c] = v1;
    }
}

// ---------------------------------------------------------------------------
extern "C" void kernel_launch(void* const* d_in, const int* in_sizes, int n_in,
                              void* d_out, int out_size)
{
    (void)in_sizes; (void)n_in; (void)out_size;
    const float* x      = (const float*)d_in[0];
    const float* W_attn = (const float*)d_in[1];
    const float* b_attn = (const float*)d_in[2];
    const float* W_proj = (const float*)d_in[3];
    const float* b_proj = (const float*)d_in[4];
    float* out = (float*)d_out;

    float *xr = nullptr, *war = nullptr, *wpr = nullptr, *gy = nullptr;
    cudaGetSymbolAddress((void**)&xr, g_xr);
    cudaGetSymbolAddress((void**)&war, g_war);
    cudaGetSymbolAddress((void**)&wpr, g_wpr);
    cudaGetSymbolAddress((void**)&gy, g_y);

    static bool attr_done = false;
    if (!attr_done) {
        cudaFuncSetAttribute(mma_gemm<0, N3>, cudaFuncAttributeMaxDynamicSharedMemorySize, SMEM_GEMM);
        cudaFuncSetAttribute(mma_gemm<1, DD>, cudaFuncAttributeMaxDynamicSharedMemorySize, SMEM_GEMM);
        cudaFuncSetAttribute(attn_tc, cudaFuncAttributeMaxDynamicSharedMemorySize, SMEM_ATTN);
        attr_done = true;
    }

    // 0) pre-round inputs to tf32 (RNE) — hoists all CVTs out of hot loops
    round_tf32<<<592, 256>>>((const float4*)x, (float4*)xr, MM * DD / 4);
    round_tf32<<<592, 256>>>((const float4*)W_attn, (float4*)war, DD * N3 / 4);
    round_tf32<<<592, 256>>>((const float4*)W_proj, (float4*)wpr, DD * DD / 4);

    // 1) QKV projection + head-layout scatter (writes tf32-rounded q/k/v)
    mma_gemm<0, N3><<<dim3(N3 / 128, MM / 128), 256, SMEM_GEMM>>>(xr, war, b_attn, nullptr);

    // 2) causal flash attention (writes tf32-rounded y)
    attn_tc<<<dim3(TT / 128, HH, BB), 256, SMEM_ATTN>>>();

    // 3) output projection
    mma_gemm<1, DD><<<dim3(DD / 128, MM / 128), 256, SMEM_GEMM>>>(gy, wpr, b_proj, out);
}

// round 7
// speedup vs baseline: 1.7865x; 1.1755x over previous
#include <cuda_runtime.h>
#include <math.h>
#include <stdint.h>

#define BB 4
#define TT 2048
#define DD 1024
#define HH 16
#define HD 64
#define MM (BB*TT)           // 8192
#define N3 (3*DD)            // 3072

// Scratch (device globals: allocation-guard-safe)
__device__ float g_q[BB*HH*TT*HD];   // [B,H,T,hd]  (tf32-rounded)
__device__ float g_k[BB*HH*TT*HD];
__device__ float g_v[BB*HH*TT*HD];
__device__ float g_y[MM*DD];         // [B,T,D]     (tf32-rounded)
__device__ float g_xr[MM*DD];        // tf32-rounded x
__device__ float g_war[DD*N3];       // tf32-rounded W_attn
__device__ float g_wpr[DD*DD];       // tf32-rounded W_proj

__device__ __forceinline__ float tf32r(float x) {
    uint32_t u;
    asm("cvt.rna.tf32.f32 %0, %1;" : "=r"(u) : "f"(x));
    return __uint_as_float(u);
}
__device__ __forceinline__ uint32_t f2b(float x) { return __float_as_uint(x); }
__device__ __forceinline__ uint32_t saddr(const void* p) {
    return (uint32_t)__cvta_generic_to_shared(p);
}

#define MMA_TF32(d, a, b) \
    asm volatile("mma.sync.aligned.m16n8k8.row.col.f32.tf32.tf32.f32 " \
        "{%0,%1,%2,%3}, {%4,%5,%6,%7}, {%8,%9}, {%0,%1,%2,%3};" \
        : "+f"((d)[0]), "+f"((d)[1]), "+f"((d)[2]), "+f"((d)[3]) \
        : "r"((a)[0]), "r"((a)[1]), "r"((a)[2]), "r"((a)[3]), \
          "r"((b)[0]), "r"((b)[1]))

#define LDSM_X4(r0, r1, r2, r3, a) \
    asm volatile("ldmatrix.sync.aligned.m8n8.x4.shared.b16 {%0,%1,%2,%3}, [%4];" \
        : "=r"(r0), "=r"(r1), "=r"(r2), "=r"(r3) : "r"(a))

// ---------------------------------------------------------------------------
// Elementwise tf32 RNE rounding pass
// ---------------------------------------------------------------------------
__global__ __launch_bounds__(256)
void round_tf32(const float4* __restrict__ src, float4* __restrict__ dst, int n4)
{
    int i = blockIdx.x * blockDim.x + threadIdx.x;
    const int stride = gridDim.x * blockDim.x;
    for (; i < n4; i += stride) {
        float4 v = src[i];
        v.x = tf32r(v.x); v.y = tf32r(v.y); v.z = tf32r(v.z); v.w = tf32r(v.w);
        dst[i] = v;
    }
}

// ---------------------------------------------------------------------------
// Tensor-core TF32 GEMM: C[M,N] = A[M,1024]*B[1024,N]+bias
// CTA 128x128, 8 warps (2M x 4N), warp tile 64x32, KSTAGE=16, double buffer.
// A tile stored [m][k] (stride 20, conflict-free) -> fragments via ldmatrix.x4.
// B tile [k][n] stride 136, scalar frag loads (conflict-free).
// ---------------------------------------------------------------------------
#define ASTRIDE 20
#define BSTRIDE 136

template<int MODE, int NTOT>
__global__ __launch_bounds__(256, 2)
void mma_gemm(const float* __restrict__ A, const float* __restrict__ B,
              const float* __restrict__ bias, float* __restrict__ C)
{
    __shared__ float As[2][128][ASTRIDE];
    __shared__ float Bs[2][16][BSTRIDE];

    const int tid = threadIdx.x;
    const int lane = tid & 31;
    const int wid = tid >> 5;
    const int warp_m = wid >> 2;
    const int warp_n = wid & 3;
    const int g = lane >> 2;
    const int tg = lane & 3;
    const int bx = blockIdx.x, by = blockIdx.y;

    const float* Ag = A + (size_t)(by * 128) * 1024;
    const float* Bg = B + bx * 128;

    const int am0 = tid >> 2;            // 0..63
    const int am1 = am0 + 64;
    const int akc = (tid & 3) << 2;      // 0,4,8,12
    const int bk0 = tid >> 5;            // 0..7
    const int bk1 = bk0 + 8;
    const int bnc = (tid & 31) << 2;     // 0..124

    // ldmatrix lane-address components for A fragments
    const int lrow = (lane & 7) + ((lane >> 3) & 1) * 8;   // row within 16-row frag
    const int lcol = (lane >> 4) * 4;                      // 0 or 4 (k half)

    float acc[4][4][4];
    #pragma unroll
    for (int i = 0; i < 4; i++)
        #pragma unroll
        for (int j = 0; j < 4; j++)
            #pragma unroll
            for (int r = 0; r < 4; r++) acc[i][j][r] = 0.0f;

    float4 ra0 = *(const float4*)&Ag[(size_t)am0 * 1024 + akc];
    float4 ra1 = *(const float4*)&Ag[(size_t)am1 * 1024 + akc];
    float4 rb0 = *(const float4*)&Bg[(size_t)bk0 * NTOT + bnc];
    float4 rb1 = *(const float4*)&Bg[(size_t)bk1 * NTOT + bnc];

    for (int s = 0; s < 64; s++) {
        const int buf = s & 1;

        *(float4*)&As[buf][am0][akc] = ra0;      // direct copy (no transpose)
        *(float4*)&As[buf][am1][akc] = ra1;
        *(float4*)&Bs[buf][bk0][bnc] = rb0;
        *(float4*)&Bs[buf][bk1][bnc] = rb1;
        __syncthreads();

        if (s < 63) {
            const int kb = (s + 1) * 16;
            ra0 = *(const float4*)&Ag[(size_t)am0 * 1024 + kb + akc];
            ra1 = *(const float4*)&Ag[(size_t)am1 * 1024 + kb + akc];
            rb0 = *(const float4*)&Bg[(size_t)(kb + bk0) * NTOT + bnc];
            rb1 = *(const float4*)&Bg[(size_t)(kb + bk1) * NTOT + bnc];
        }

        #pragma unroll
        for (int ks = 0; ks < 2; ks++) {
            const int k8 = ks * 8;
            uint32_t af[4][4];
            #pragma unroll
            for (int mi = 0; mi < 4; mi++) {
                const uint32_t a = saddr(&As[buf][warp_m * 64 + mi * 16 + lrow][k8 + lcol]);
                LDSM_X4(af[mi][0], af[mi][1], af[mi][2], af[mi][3], a);
            }
            uint32_t bf[4][2];
            #pragma unroll
            for (int ni = 0; ni < 4; ni++) {
                const int bn = warp_n * 32 + ni * 8;
                bf[ni][0] = f2b(Bs[buf][k8 + tg][bn + g]);
                bf[ni][1] = f2b(Bs[buf][k8 + tg + 4][bn + g]);
            }
            #pragma unroll
            for (int mi = 0; mi < 4; mi++)
                #pragma unroll
                for (int ni = 0; ni < 4; ni++)
                    MMA_TF32(acc[mi][ni], af[mi], bf[ni]);
        }
    }

    #pragma unroll
    for (int mi = 0; mi < 4; mi++) {
        #pragma unroll
        for (int ni = 0; ni < 4; ni++) {
            const int n = bx * 128 + warp_n * 32 + ni * 8 + 2 * tg;
            const float b0 = bias[n], b1 = bias[n + 1];
            #pragma unroll
            for (int p = 0; p < 2; p++) {
                const int m = by * 128 + warp_m * 64 + mi * 16 + g + p * 8;
                float2 v;
                if (MODE == 0) {
                    v.x = tf32r(acc[mi][ni][2 * p + 0] + b0);
                    v.y = tf32r(acc[mi][ni][2 * p + 1] + b1);
                    const int b_ = m >> 11;
                    const int t_ = m & 2047;
                    const int sel = n >> 10;
                    const int d = n & 1023;
                    float* dst = (sel == 0) ? g_q : ((sel == 1) ? g_k : g_v);
                    *(float2*)&dst[((size_t)(b_ * 16 + (d >> 6)) * 2048 + t_) * 64 + (d & 63)] = v;
                } else {
                    v.x = acc[mi][ni][2 * p + 0] + b0;
                    v.y = acc[mi][ni][2 * p + 1] + b1;
                    *(float2*)&C[(size_t)m * NTOT + n] = v;
                }
            }
        }
    }
}

// ---------------------------------------------------------------------------
// Tensor-core flash attention (causal, tf32 mma + ldmatrix fragments).
// Ks[key][hd] (K-frags via ldmatrix), Vt[hd][key] (transposed staging,
// V-frags via ldmatrix), Pw[qrow][key] (P-frags via ldmatrix).
// ---------------------------------------------------------------------------
#define ASTR 68
#define SMEM_ATTN ((2 * 64 * ASTR + 8 * 16 * ASTR) * 4)   // 69632 B

__global__ __launch_bounds__(256, 2)
void attn_tc()
{
    extern __shared__ float smf[];
    float* Ks = smf;                        // [64][68]  K[key][hd]
    float* Vt = smf + 64 * ASTR;            // [64][68]  V^T[hd][key]
    float* Ps = smf + 2 * 64 * ASTR;        // [8][16][68] per-warp P / Q stage

    const int tid  = threadIdx.x;
    const int lane = tid & 31;
    const int wid  = tid >> 5;
    const int g    = lane >> 2;
    const int tg   = lane & 3;
    const int qt = blockIdx.x;
    const int h  = blockIdx.y;
    const int b  = blockIdx.z;

    const float* qb = g_q + (size_t)(b * HH + h) * TT * HD;
    const float* kb = g_k + (size_t)(b * HH + h) * TT * HD;
    const float* vb = g_v + (size_t)(b * HH + h) * TT * HD;

    float* Pw = Ps + wid * 16 * ASTR;

    // ldmatrix lane-address components
    const int arow = (lane & 7) + ((lane >> 3) & 1) * 8;   // A-frag row
    const int acol = (lane >> 4) * 4;                      // A-frag k-half
    const int brow = (lane & 7) + ((lane >> 4) & 1) * 8;   // B-frag row (n)
    const int bcol = ((lane >> 3) & 1) * 4;                // B-frag k-half

    // ---- load Q fragments into registers (once) ----
    uint32_t Qf[8][4];
    {
        const int r = lane >> 1;
        const int c = (lane & 1) * 32;
        const float* qrow = qb + (size_t)(qt * 128 + wid * 16 + r) * 64 + c;
        #pragma unroll
        for (int i = 0; i < 8; i++)
            *(float4*)&Pw[r * ASTR + c + i * 4] = *(const float4*)&qrow[i * 4];
        __syncwarp();
        #pragma unroll
        for (int ks = 0; ks < 8; ks++) {
            const uint32_t a = saddr(&Pw[arow * ASTR + ks * 8 + acol]);
            LDSM_X4(Qf[ks][0], Qf[ks][1], Qf[ks][2], Qf[ks][3], a);
        }
    }

    float O[8][4];
    #pragma unroll
    for (int ni = 0; ni < 8; ni++)
        #pragma unroll
        for (int r = 0; r < 4; r++) O[ni][r] = 0.0f;
    float mi0 = -INFINITY, mi1 = -INFINITY, li0 = 0.0f, li1 = 0.0f;

    const int row0 = qt * 128 + wid * 16 + g;
    const int row1 = row0 + 8;
    const int wrow_min = qt * 128 + wid * 16;
    const float scale = 0.125f;
    const int nkt = 2 * qt + 2;

    // V-transpose staging mapping: key distinct per lane -> conflict-free STS
    const int vkey = tid & 63;
    const int vhc  = (tid >> 6) << 4;     // 0,16,32,48

    for (int kt = 0; kt < nkt; kt++) {
        __syncthreads();
        {
            // K: direct [key][hd] float4 copy
            const int r = tid >> 2;
            const int c = (tid & 3) << 4;
            const float* krow = kb + (size_t)(kt * 64 + r) * 64 + c;
            #pragma unroll
            for (int i = 0; i < 4; i++)
                *(float4*)&Ks[r * ASTR + c + i * 4] = *(const float4*)&krow[i * 4];
            // V: transpose into Vt[hd][key]
            const float* vrow = vb + (size_t)(kt * 64 + vkey) * 64 + vhc;
            #pragma unroll
            for (int i = 0; i < 4; i++) {
                float4 vv = *(const float4*)&vrow[i * 4];
                Vt[(vhc + i * 4 + 0) * ASTR + vkey] = vv.x;
                Vt[(vhc + i * 4 + 1) * ASTR + vkey] = vv.y;
                Vt[(vhc + i * 4 + 2) * ASTR + vkey] = vv.z;
                Vt[(vhc + i * 4 + 3) * ASTR + vkey] = vv.w;
            }
        }
        __syncthreads();

        // ---- S = Q K^T ----
        float S[8][4];
        #pragma unroll
        for (int ni = 0; ni < 8; ni++)
            #pragma unroll
            for (int r = 0; r < 4; r++) S[ni][r] = 0.0f;

        #pragma unroll
        for (int ks = 0; ks < 8; ks++) {
            uint32_t bf[8][2];
            #pragma unroll
            for (int np = 0; np < 4; np++) {
                const uint32_t a = saddr(&Ks[(np * 16 + brow) * ASTR + ks * 8 + bcol]);
                LDSM_X4(bf[2 * np][0], bf[2 * np][1], bf[2 * np + 1][0], bf[2 * np + 1][1], a);
            }
            #pragma unroll
            for (int ni = 0; ni < 8; ni++)
                MMA_TF32(S[ni], Qf[ks], bf[ni]);
        }

        if (kt * 64 + 63 > wrow_min) {
            #pragma unroll
            for (int ni = 0; ni < 8; ni++) {
                const int c0 = kt * 64 + ni * 8 + 2 * tg;
                S[ni][0] = (c0     > row0) ? -INFINITY : S[ni][0] * scale;
                S[ni][1] = (c0 + 1 > row0) ? -INFINITY : S[ni][1] * scale;
                S[ni][2] = (c0     > row1) ? -INFINITY : S[ni][2] * scale;
                S[ni][3] = (c0 + 1 > row1) ? -INFINITY : S[ni][3] * scale;
            }
        } else {
            #pragma unroll
            for (int ni = 0; ni < 8; ni++) {
                S[ni][0] *= scale; S[ni][1] *= scale;
                S[ni][2] *= scale; S[ni][3] *= scale;
            }
        }

        float m0 = -INFINITY, m1 = -INFINITY;
        #pragma unroll
        for (int ni = 0; ni < 8; ni++) {
            m0 = fmaxf(m0, fmaxf(S[ni][0], S[ni][1]));
            m1 = fmaxf(m1, fmaxf(S[ni][2], S[ni][3]));
        }
        m0 = fmaxf(m0, __shfl_xor_sync(0xffffffffu, m0, 1));
        m0 = fmaxf(m0, __shfl_xor_sync(0xffffffffu, m0, 2));
        m1 = fmaxf(m1, __shfl_xor_sync(0xffffffffu, m1, 1));
        m1 = fmaxf(m1, __shfl_xor_sync(0xffffffffu, m1, 2));
        const float mn0 = fmaxf(mi0, m0);
        const float mn1 = fmaxf(mi1, m1);
        const float a0 = __expf(mi0 - mn0);
        const float a1 = __expf(mi1 - mn1);
        mi0 = mn0; mi1 = mn1;

        float rs0 = 0.0f, rs1 = 0.0f;
        #pragma unroll
        for (int ni = 0; ni < 8; ni++) {
            const float p00 = __expf(S[ni][0] - mn0);
            const float p01 = __expf(S[ni][1] - mn0);
            const float p10 = __expf(S[ni][2] - mn1);
            const float p11 = __expf(S[ni][3] - mn1);
            rs0 += p00 + p01;
            rs1 += p10 + p11;
            float2 t0; t0.x = tf32r(p00); t0.y = tf32r(p01);
            *(float2*)&Pw[g * ASTR + ni * 8 + 2 * tg] = t0;
            float2 t1; t1.x = tf32r(p10); t1.y = tf32r(p11);
            *(float2*)&Pw[(g + 8) * ASTR + ni * 8 + 2 * tg] = t1;
            O[ni][0] *= a0; O[ni][1] *= a0;
            O[ni][2] *= a1; O[ni][3] *= a1;
        }
        rs0 += __shfl_xor_sync(0xffffffffu, rs0, 1);
        rs0 += __shfl_xor_sync(0xffffffffu, rs0, 2);
        rs1 += __shfl_xor_sync(0xffffffffu, rs1, 1);
        rs1 += __shfl_xor_sync(0xffffffffu, rs1, 2);
        li0 = li0 * a0 + rs0;
        li1 = li1 * a1 + rs1;
        __syncwarp();

        // ---- O += P V ----
        #pragma unroll
        for (int ks = 0; ks < 8; ks++) {
            uint32_t af[4];
            {
                const uint32_t a = saddr(&Pw[arow * ASTR + ks * 8 + acol]);
                LDSM_X4(af[0], af[1], af[2], af[3], a);
            }
            uint32_t bf[8][2];
            #pragma unroll
            for (int np = 0; np < 4; np++) {
                const uint32_t a = saddr(&Vt[(np * 16 + brow) * ASTR + ks * 8 + bcol]);
                LDSM_X4(bf[2 * np][0], bf[2 * np][1], bf[2 * np + 1][0], bf[2 * np + 1][1], a);
            }
            #pragma unroll
            for (int ni = 0; ni < 8; ni++)
                MMA_TF32(O[ni], af, bf[ni]);
        }
    }

    const float inv0 = 1.0f / li0;
    const float inv1 = 1.0f / li1;
    float* y0 = g_y + (size_t)(b * TT + row0) * DD + h * HD;
    float* y1 = g_y + (size_t)(b * TT + row1) * DD + h * HD;
    #pragma unroll
    for (int ni = 0; ni < 8; ni++) {
        const int c = ni * 8 + 2 * tg;
        float2 v0; v0.x = tf32r(O[ni][0] * inv0); v0.y = tf32r(O[ni][1] * inv0);
        *(float2*)&y0[c] = v0;
        float2 v1; v1.x = tf32r(O[ni][2] * inv1); v1.y = tf32r(O[ni][3] * inv1);
        *(float2*)&y1[c] = v1;
    }
}

// ---------------------------------------------------------------------------
extern "C" void kernel_launch(void* const* d_in, const int* in_sizes, int n_in,
                              void* d_out, int out_size)
{
    (void)in_sizes; (void)n_in; (void)out_size;
    const float* x      = (const float*)d_in[0];
    const float* W_attn = (const float*)d_in[1];
    const float* b_attn = (const float*)d_in[2];
    const float* W_proj = (const float*)d_in[3];
    const float* b_proj = (const float*)d_in[4];
    float* out = (float*)d_out;

    float *xr = nullptr, *war = nullptr, *wpr = nullptr, *gy = nullptr;
    cudaGetSymbolAddress((void**)&xr, g_xr);
    cudaGetSymbolAddress((void**)&war, g_war);
    cudaGetSymbolAddress((void**)&wpr, g_wpr);
    cudaGetSymbolAddress((void**)&gy, g_y);

    static bool attr_done = false;
    if (!attr_done) {
        cudaFuncSetAttribute(attn_tc, cudaFuncAttributeMaxDynamicSharedMemorySize, SMEM_ATTN);
        attr_done = true;
    }

    // 0) pre-round inputs to tf32 (RNE)
    round_tf32<<<592, 256>>>((const float4*)x, (float4*)xr, MM * DD / 4);
    round_tf32<<<592, 256>>>((const float4*)W_attn, (float4*)war, DD * N3 / 4);
    round_tf32<<<592, 256>>>((const float4*)W_proj, (float4*)wpr, DD * DD / 4);

    // 1) QKV projection + head-layout scatter (writes tf32-rounded q/k/v)
    mma_gemm<0, N3><<<dim3(N3 / 128, MM / 128), 256>>>(xr, war, b_attn, nullptr);

    // 2) causal flash attention (ldmatrix + mma)
    attn_tc<<<dim3(TT / 128, HH, BB), 256, SMEM_ATTN>>>();

    // 3) output projection
    mma_gemm<1, DD><<<dim3(DD / 128, MM / 128), 256>>>(gy, wpr, b_proj, out);
}

// round 8
// speedup vs baseline: 3.5857x; 2.0072x over previous
#include <cuda_runtime.h>
#include <cuda_fp16.h>
#include <math.h>
#include <stdint.h>

#define BB 4
#define TT 2048
#define DD 1024
#define HH 16
#define HD 64
#define MM (BB*TT)           // 8192
#define N3 (3*DD)            // 3072

// Scratch (device globals: allocation-guard-safe)
__device__ __half g_qh[BB*HH*TT*HD];   // [B,H,T,hd]
__device__ __half g_kh[BB*HH*TT*HD];
__device__ __half g_vh[BB*HH*TT*HD];
__device__ __half g_yh[MM*DD];         // [B,T,D]
__device__ __half g_xh[MM*DD];         // fp16 x
__device__ __half g_wah[DD*N3];        // fp16 W_attn
__device__ __half g_wph[DD*DD];        // fp16 W_proj

__device__ __forceinline__ uint32_t saddr(const void* p) {
    return (uint32_t)__cvta_generic_to_shared(p);
}

#define MMA_F16(d, a, b) \
    asm volatile("mma.sync.aligned.m16n8k16.row.col.f32.f16.f16.f32 " \
        "{%0,%1,%2,%3}, {%4,%5,%6,%7}, {%8,%9}, {%0,%1,%2,%3};" \
        : "+f"((d)[0]), "+f"((d)[1]), "+f"((d)[2]), "+f"((d)[3]) \
        : "r"((a)[0]), "r"((a)[1]), "r"((a)[2]), "r"((a)[3]), \
          "r"((b)[0]), "r"((b)[1]))

#define LDSM_X4(r0, r1, r2, r3, a) \
    asm volatile("ldmatrix.sync.aligned.m8n8.x4.shared.b16 {%0,%1,%2,%3}, [%4];" \
        : "=r"(r0), "=r"(r1), "=r"(r2), "=r"(r3) : "r"(a))

#define LDSM_X4_T(r0, r1, r2, r3, a) \
    asm volatile("ldmatrix.sync.aligned.m8n8.x4.trans.shared.b16 {%0,%1,%2,%3}, [%4];" \
        : "=r"(r0), "=r"(r1), "=r"(r2), "=r"(r3) : "r"(a))

// ---------------------------------------------------------------------------
// fp32 -> fp16 conversion pass
// ---------------------------------------------------------------------------
__global__ __launch_bounds__(256)
void f2h(const float4* __restrict__ src, __half2* __restrict__ dst, int n4)
{
    int i = blockIdx.x * blockDim.x + threadIdx.x;
    const int stride = gridDim.x * blockDim.x;
    for (; i < n4; i += stride) {
        float4 v = src[i];
        dst[2 * i + 0] = __floats2half2_rn(v.x, v.y);
        dst[2 * i + 1] = __floats2half2_rn(v.z, v.w);
    }
}

// ---------------------------------------------------------------------------
// fp16 tensor-core GEMM: C[M,N] = A[M,1024]*B[1024,N]+bias (fp32 accum)
// CTA 128x128, 8 warps (2M x 4N), warp tile 64x32, KSTAGE=32, double buffer.
// A [m][k] stride 40h; B [k][n] stride 136h. A/Q frags non-trans LDSM,
// B frags trans LDSM. All conflict-free.
// MODE 0: scatter fp16 q/k/v. MODE 1: fp32 C.
// ---------------------------------------------------------------------------
template<int MODE, int NTOT>
__global__ __launch_bounds__(256, 2)
void mma_gemm(const __half* __restrict__ A, const __half* __restrict__ B,
              const float* __restrict__ bias, float* __restrict__ C)
{
    __shared__ __half As[2][128][40];
    __shared__ __half Bs[2][32][136];

    const int tid = threadIdx.x;
    const int lane = tid & 31;
    const int wid = tid >> 5;
    const int warp_m = wid >> 2;
    const int warp_n = wid & 3;
    const int g = lane >> 2;
    const int tg = lane & 3;
    const int bx = blockIdx.x, by = blockIdx.y;

    const __half* Ag = A + (size_t)(by * 128) * 1024;
    const __half* Bg = B + bx * 128;

    // staging mapping (uint4 = 8 halves)
    const int ar  = tid >> 2;            // 0..63 (and +64)
    const int akc = (tid & 3) << 3;      // 0,8,16,24
    const int br  = tid >> 4;            // 0..15 (and +16)
    const int bnc = (tid & 15) << 3;     // 0..120

    // ldmatrix lane-address components
    const int lrow = (lane & 7) + ((lane >> 3) & 1) * 8;   // A row within 16
    const int lch  = ((lane >> 4) & 1) * 8;                // A k-half (halves)
    const int trow = (lane & 7) + ((lane >> 3) & 1) * 8;   // B k-row within 16
    const int tcn  = ((lane >> 4) & 1) * 8;                // B n-offset (halves)

    float acc[4][4][4];
    #pragma unroll
    for (int i = 0; i < 4; i++)
        #pragma unroll
        for (int j = 0; j < 4; j++)
            #pragma unroll
            for (int r = 0; r < 4; r++) acc[i][j][r] = 0.0f;

    uint4 ra0 = *(const uint4*)&Ag[(size_t)ar * 1024 + akc];
    uint4 ra1 = *(const uint4*)&Ag[(size_t)(ar + 64) * 1024 + akc];
    uint4 rb0 = *(const uint4*)&Bg[(size_t)br * NTOT + bnc];
    uint4 rb1 = *(const uint4*)&Bg[(size_t)(br + 16) * NTOT + bnc];

    for (int s = 0; s < 32; s++) {
        const int buf = s & 1;

        *(uint4*)&As[buf][ar][akc]       = ra0;
        *(uint4*)&As[buf][ar + 64][akc]  = ra1;
        *(uint4*)&Bs[buf][br][bnc]       = rb0;
        *(uint4*)&Bs[buf][br + 16][bnc]  = rb1;
        __syncthreads();

        if (s < 31) {
            const int kb = (s + 1) * 32;
            ra0 = *(const uint4*)&Ag[(size_t)ar * 1024 + kb + akc];
            ra1 = *(const uint4*)&Ag[(size_t)(ar + 64) * 1024 + kb + akc];
            rb0 = *(const uint4*)&Bg[(size_t)(kb + br) * NTOT + bnc];
            rb1 = *(const uint4*)&Bg[(size_t)(kb + br + 16) * NTOT + bnc];
        }

        #pragma unroll
        for (int ks = 0; ks < 2; ks++) {
            const int k16 = ks * 16;
            uint32_t af[4][4];
            #pragma unroll
            for (int mi = 0; mi < 4; mi++) {
                const uint32_t a = saddr(&As[buf][warp_m * 64 + mi * 16 + lrow][k16 + lch]);
                LDSM_X4(af[mi][0], af[mi][1], af[mi][2], af[mi][3], a);
            }
            uint32_t bf[4][2];
            #pragma unroll
            for (int nn = 0; nn < 2; nn++) {
                const uint32_t a = saddr(&Bs[buf][k16 + trow][warp_n * 32 + nn * 16 + tcn]);
                LDSM_X4_T(bf[2 * nn][0], bf[2 * nn][1], bf[2 * nn + 1][0], bf[2 * nn + 1][1], a);
            }
            #pragma unroll
            for (int mi = 0; mi < 4; mi++)
                #pragma unroll
                for (int ni = 0; ni < 4; ni++)
                    MMA_F16(acc[mi][ni], af[mi], bf[ni]);
        }
    }

    #pragma unroll
    for (int mi = 0; mi < 4; mi++) {
        #pragma unroll
        for (int ni = 0; ni < 4; ni++) {
            const int n = bx * 128 + warp_n * 32 + ni * 8 + 2 * tg;
            const float b0 = bias[n], b1 = bias[n + 1];
            #pragma unroll
            for (int p = 0; p < 2; p++) {
                const int m = by * 128 + warp_m * 64 + mi * 16 + g + p * 8;
                const float vx = acc[mi][ni][2 * p + 0] + b0;
                const float vy = acc[mi][ni][2 * p + 1] + b1;
                if (MODE == 0) {
                    const int b_ = m >> 11;
                    const int t_ = m & 2047;
                    const int sel = n >> 10;
                    const int d = n & 1023;
                    __half* dst = (sel == 0) ? g_qh : ((sel == 1) ? g_kh : g_vh);
                    *(__half2*)&dst[((size_t)(b_ * 16 + (d >> 6)) * 2048 + t_) * 64 + (d & 63)] =
                        __floats2half2_rn(vx, vy);
                } else {
                    float2 v; v.x = vx; v.y = vy;
                    *(float2*)&C[(size_t)m * NTOT + n] = v;
                }
            }
        }
    }
}

// ---------------------------------------------------------------------------
// fp16 tensor-core flash attention (causal). CTA = 128 queries of (b,h),
// 8 warps x 16 query rows. K/V tiles [64][72] halves, natural [key][hd];
// K frags non-trans LDSM, V frags trans LDSM (no transpose staging).
// ---------------------------------------------------------------------------
#define PSTR 72

__global__ __launch_bounds__(256, 2)
void attn_tc()
{
    __shared__ __half Ks[64][PSTR];
    __shared__ __half Vs[64][PSTR];
    __shared__ __half Ps[8][16][PSTR];

    const int tid  = threadIdx.x;
    const int lane = tid & 31;
    const int wid  = tid >> 5;
    const int g    = lane >> 2;
    const int tg   = lane & 3;
    const int qt = blockIdx.x;
    const int h  = blockIdx.y;
    const int b  = blockIdx.z;

    const __half* qb = g_qh + (size_t)(b * HH + h) * TT * HD;
    const __half* kb = g_kh + (size_t)(b * HH + h) * TT * HD;
    const __half* vb = g_vh + (size_t)(b * HH + h) * TT * HD;

    __half (*Pw)[PSTR] = Ps[wid];

    // ldmatrix lane-address components
    const int arow = (lane & 7) + ((lane >> 3) & 1) * 8;   // A-frag m-row
    const int ach  = ((lane >> 4) & 1) * 8;                // A-frag k-half
    const int krow = (lane & 7) + ((lane >> 4) & 1) * 8;   // K-frag n-row
    const int kch  = ((lane >> 3) & 1) * 8;                // K-frag k-half
    const int vrow = (lane & 7) + ((lane >> 3) & 1) * 8;   // V-frag k-row
    const int vcn  = ((lane >> 4) & 1) * 8;                // V-frag n-offset

    // ---- load Q fragments into registers (once) ----
    uint32_t Qf[4][4];
    {
        const int r = lane >> 1;
        const int c = (lane & 1) * 32;
        const __half* qrow = qb + (size_t)(qt * 128 + wid * 16 + r) * 64 + c;
        #pragma unroll
        for (int i = 0; i < 4; i++)
            *(uint4*)&Pw[r][c + i * 8] = *(const uint4*)&qrow[i * 8];
        __syncwarp();
        #pragma unroll
        for (int ks = 0; ks < 4; ks++) {
            const uint32_t a = saddr(&Pw[arow][ks * 16 + ach]);
            LDSM_X4(Qf[ks][0], Qf[ks][1], Qf[ks][2], Qf[ks][3], a);
        }
    }

    float O[8][4];
    #pragma unroll
    for (int ni = 0; ni < 8; ni++)
        #pragma unroll
        for (int r = 0; r < 4; r++) O[ni][r] = 0.0f;
    float mi0 = -INFINITY, mi1 = -INFINITY, li0 = 0.0f, li1 = 0.0f;

    const int row0 = qt * 128 + wid * 16 + g;
    const int row1 = row0 + 8;
    const int wrow_min = qt * 128 + wid * 16;
    const float scale = 0.125f;
    const int nkt = 2 * qt + 2;

    // staging mapping: uint4 = 8 halves; 64 rows x 8 chunks = 512, 2/thread
    const int sr = tid >> 2;             // 0..63
    const int sc = (tid & 3) << 3;       // 0,8,16,24  (+32 for second)

    for (int kt = 0; kt < nkt; kt++) {
        __syncthreads();
        {
            const __half* krow_p = kb + (size_t)(kt * 64 + sr) * 64;
            const __half* vrow_p = vb + (size_t)(kt * 64 + sr) * 64;
            *(uint4*)&Ks[sr][sc]      = *(const uint4*)&krow_p[sc];
            *(uint4*)&Ks[sr][sc + 32] = *(const uint4*)&krow_p[sc + 32];
            *(uint4*)&Vs[sr][sc]      = *(const uint4*)&vrow_p[sc];
            *(uint4*)&Vs[sr][sc + 32] = *(const uint4*)&vrow_p[sc + 32];
        }
        __syncthreads();

        // ---- S = Q K^T ----
        float S[8][4];
        #pragma unroll
        for (int ni = 0; ni < 8; ni++)
            #pragma unroll
            for (int r = 0; r < 4; r++) S[ni][r] = 0.0f;

        #pragma unroll
        for (int ks = 0; ks < 4; ks++) {
            uint32_t bf[8][2];
            #pragma unroll
            for (int np = 0; np < 4; np++) {
                const uint32_t a = saddr(&Ks[np * 16 + krow][ks * 16 + kch]);
                LDSM_X4(bf[2 * np][0], bf[2 * np][1], bf[2 * np + 1][0], bf[2 * np + 1][1], a);
            }
            #pragma unroll
            for (int ni = 0; ni < 8; ni++)
                MMA_F16(S[ni], Qf[ks], bf[ni]);
        }

        if (kt * 64 + 63 > wrow_min) {
            #pragma unroll
            for (int ni = 0; ni < 8; ni++) {
                const int c0 = kt * 64 + ni * 8 + 2 * tg;
                S[ni][0] = (c0     > row0) ? -INFINITY : S[ni][0] * scale;
                S[ni][1] = (c0 + 1 > row0) ? -INFINITY : S[ni][1] * scale;
                S[ni][2] = (c0     > row1) ? -INFINITY : S[ni][2] * scale;
                S[ni][3] = (c0 + 1 > row1) ? -INFINITY : S[ni][3] * scale;
            }
        } else {
            #pragma unroll
            for (int ni = 0; ni < 8; ni++) {
                S[ni][0] *= scale; S[ni][1] *= scale;
                S[ni][2] *= scale; S[ni][3] *= scale;
            }
        }

        float m0 = -INFINITY, m1 = -INFINITY;
        #pragma unroll
        for (int ni = 0; ni < 8; ni++) {
            m0 = fmaxf(m0, fmaxf(S[ni][0], S[ni][1]));
            m1 = fmaxf(m1, fmaxf(S[ni][2], S[ni][3]));
        }
        m0 = fmaxf(m0, __shfl_xor_sync(0xffffffffu, m0, 1));
        m0 = fmaxf(m0, __shfl_xor_sync(0xffffffffu, m0, 2));
        m1 = fmaxf(m1, __shfl_xor_sync(0xffffffffu, m1, 1));
        m1 = fmaxf(m1, __shfl_xor_sync(0xffffffffu, m1, 2));
        const float mn0 = fmaxf(mi0, m0);
        const float mn1 = fmaxf(mi1, m1);
        const float a0 = __expf(mi0 - mn0);
        const float a1 = __expf(mi1 - mn1);
        mi0 = mn0; mi1 = mn1;

        float rs0 = 0.0f, rs1 = 0.0f;
        #pragma unroll
        for (int ni = 0; ni < 8; ni++) {
            const float p00 = __expf(S[ni][0] - mn0);
            const float p01 = __expf(S[ni][1] - mn0);
            const float p10 = __expf(S[ni][2] - mn1);
            const float p11 = __expf(S[ni][3] - mn1);
            rs0 += p00 + p01;
            rs1 += p10 + p11;
            *(__half2*)&Pw[g][ni * 8 + 2 * tg]     = __floats2half2_rn(p00, p01);
            *(__half2*)&Pw[g + 8][ni * 8 + 2 * tg] = __floats2half2_rn(p10, p11);
            O[ni][0] *= a0; O[ni][1] *= a0;
            O[ni][2] *= a1; O[ni][3] *= a1;
        }
        rs0 += __shfl_xor_sync(0xffffffffu, rs0, 1);
        rs0 += __shfl_xor_sync(0xffffffffu, rs0, 2);
        rs1 += __shfl_xor_sync(0xffffffffu, rs1, 1);
        rs1 += __shfl_xor_sync(0xffffffffu, rs1, 2);
        li0 = li0 * a0 + rs0;
        li1 = li1 * a1 + rs1;
        __syncwarp();

        // ---- O += P V ----
        #pragma unroll
        for (int ks = 0; ks < 4; ks++) {
            uint32_t af[4];
            {
                const uint32_t a = saddr(&Pw[arow][ks * 16 + ach]);
                LDSM_X4(af[0], af[1], af[2], af[3], a);
            }
            uint32_t bf[8][2];
            #pragma unroll
            for (int np = 0; np < 4; np++) {
                const uint32_t a = saddr(&Vs[ks * 16 + vrow][np * 16 + vcn]);
                LDSM_X4_T(bf[2 * np][0], bf[2 * np][1], bf[2 * np + 1][0], bf[2 * np + 1][1], a);
            }
            #pragma unroll
            for (int ni = 0; ni < 8; ni++)
                MMA_F16(O[ni], af, bf[ni]);
        }
    }

    const float inv0 = 1.0f / li0;
    const float inv1 = 1.0f / li1;
    __half* y0 = g_yh + (size_t)(b * TT + row0) * DD + h * HD;
    __half* y1 = g_yh + (size_t)(b * TT + row1) * DD + h * HD;
    #pragma unroll
    for (int ni = 0; ni < 8; ni++) {
        const int c = ni * 8 + 2 * tg;
        *(__half2*)&y0[c] = __floats2half2_rn(O[ni][0] * inv0, O[ni][1] * inv0);
        *(__half2*)&y1[c] = __floats2half2_rn(O[ni][2] * inv1, O[ni][3] * inv1);
    }
}

// ---------------------------------------------------------------------------
extern "C" void kernel_launch(void* const* d_in, const int* in_sizes, int n_in,
                              void* d_out, int out_size)
{
    (void)in_sizes; (void)n_in; (void)out_size;
    const float* x      = (const float*)d_in[0];
    const float* W_attn = (const float*)d_in[1];
    const float* b_attn = (const float*)d_in[2];
    const float* W_proj = (const float*)d_in[3];
    const float* b_proj = (const float*)d_in[4];
    float* out = (float*)d_out;

    __half *xh = nullptr, *wah = nullptr, *wph = nullptr, *yh = nullptr;
    cudaGetSymbolAddress((void**)&xh, g_xh);
    cudaGetSymbolAddress((void**)&wah, g_wah);
    cudaGetSymbolAddress((void**)&wph, g_wph);
    cudaGetSymbolAddress((void**)&yh, g_yh);

    // 0) convert inputs to fp16 (RNE)
    f2h<<<592, 256>>>((const float4*)x, (__half2*)xh, MM * DD / 4);
    f2h<<<592, 256>>>((const float4*)W_attn, (__half2*)wah, DD * N3 / 4);
    f2h<<<592, 256>>>((const float4*)W_proj, (__half2*)wph, DD * DD / 4);

    // 1) QKV projection + head-layout scatter (fp16 out)
    mma_gemm<0, N3><<<dim3(N3 / 128, MM / 128), 256>>>(xh, wah, b_attn, nullptr);

    // 2) causal flash attention (fp16 mma, fp32 softmax)
    attn_tc<<<dim3(TT / 128, HH, BB), 256>>>();

    // 3) output projection (fp32 out)
    mma_gemm<1, DD><<<dim3(DD / 128, MM / 128), 256>>>(yh, wph, b_proj, out);
}

// round 9
// speedup vs baseline: 3.5870x; 1.0004x over previous
#include <cuda_runtime.h>
#include <cuda_fp16.h>
#include <math.h>
#include <stdint.h>

#define BB 4
#define TT 2048
#define DD 1024
#define HH 16
#define HD 64
#define MM (BB*TT)           // 8192
#define N3 (3*DD)            // 3072

// Scratch (device globals: allocation-guard-safe)
__device__ __half g_qh[BB*HH*TT*HD];   // [B,H,T,hd]
__device__ __half g_kh[BB*HH*TT*HD];
__device__ __half g_vh[BB*HH*TT*HD];
__device__ __half g_yh[MM*DD];         // [B,T,D]
__device__ __half g_xh[MM*DD];
__device__ __half g_wah[DD*N3];
__device__ __half g_wph[DD*DD];

__device__ __forceinline__ uint32_t saddr(const void* p) {
    return (uint32_t)__cvta_generic_to_shared(p);
}

#define MMA_F16(d, a, b) \
    asm volatile("mma.sync.aligned.m16n8k16.row.col.f32.f16.f16.f32 " \
        "{%0,%1,%2,%3}, {%4,%5,%6,%7}, {%8,%9}, {%0,%1,%2,%3};" \
        : "+f"((d)[0]), "+f"((d)[1]), "+f"((d)[2]), "+f"((d)[3]) \
        : "r"((a)[0]), "r"((a)[1]), "r"((a)[2]), "r"((a)[3]), \
          "r"((b)[0]), "r"((b)[1]))

#define LDSM_X4(r0, r1, r2, r3, a) \
    asm volatile("ldmatrix.sync.aligned.m8n8.x4.shared.b16 {%0,%1,%2,%3}, [%4];" \
        : "=r"(r0), "=r"(r1), "=r"(r2), "=r"(r3) : "r"(a))

#define LDSM_X4_T(r0, r1, r2, r3, a) \
    asm volatile("ldmatrix.sync.aligned.m8n8.x4.trans.shared.b16 {%0,%1,%2,%3}, [%4];" \
        : "=r"(r0), "=r"(r1), "=r"(r2), "=r"(r3) : "r"(a))

#define CP_ASYNC(dst, src) \
    asm volatile("cp.async.cg.shared.global [%0], [%1], 16;" :: "r"(dst), "l"(src))
#define CP_COMMIT() asm volatile("cp.async.commit_group;" ::: "memory")
#define CP_WAIT0()  asm volatile("cp.async.wait_group 0;" ::: "memory")
#define CP_WAIT1()  asm volatile("cp.async.wait_group 1;" ::: "memory")

// ---------------------------------------------------------------------------
// fp32 -> fp16 conversion pass
// ---------------------------------------------------------------------------
__global__ __launch_bounds__(256)
void f2h(const float4* __restrict__ src, __half2* __restrict__ dst, int n4)
{
    int i = blockIdx.x * blockDim.x + threadIdx.x;
    const int stride = gridDim.x * blockDim.x;
    for (; i < n4; i += stride) {
        float4 v = src[i];
        dst[2 * i + 0] = __floats2half2_rn(v.x, v.y);
        dst[2 * i + 1] = __floats2half2_rn(v.z, v.w);
    }
}

// ---------------------------------------------------------------------------
// fp16 tensor-core GEMM with cp.async 3-stage pipeline.
// CTA 128x128, 8 warps (2M x 4N), warp 64x32, KSTAGE=32.
// ---------------------------------------------------------------------------
#define GEMM_SMEM ((3 * 128 * 40 + 3 * 32 * 136) * 2)   // 56832 B

template<int MODE, int NTOT>
__global__ __launch_bounds__(256, 2)
void mma_gemm(const __half* __restrict__ A, const __half* __restrict__ B,
              const float* __restrict__ bias, float* __restrict__ C)
{
    extern __shared__ __half hsm[];
    __half (*As)[128][40] = (__half (*)[128][40])hsm;
    __half (*Bs)[32][136] = (__half (*)[32][136])(hsm + 3 * 128 * 40);

    const int tid = threadIdx.x;
    const int lane = tid & 31;
    const int wid = tid >> 5;
    const int warp_m = wid >> 2;
    const int warp_n = wid & 3;
    const int g = lane >> 2;
    const int tg = lane & 3;
    const int bx = blockIdx.x, by = blockIdx.y;

    const __half* Ag = A + (size_t)(by * 128) * 1024;
    const __half* Bg = B + bx * 128;

    // cp.async mappings (16B = 8 halves per op, 4 ops/thread/stage)
    const int ar = tid >> 1;             // 0..127
    const int ac = (tid & 1) << 3;       // 0,8 (chunks at ac, ac+16)
    const int br = tid >> 3;             // 0..31
    const int bc = (tid & 7) << 3;       // 0..56 (chunks at bc, bc+64)

    // ldmatrix lane-address components
    const int lrow = (lane & 7) + ((lane >> 3) & 1) * 8;
    const int lch  = ((lane >> 4) & 1) * 8;
    const int trow = (lane & 7) + ((lane >> 3) & 1) * 8;
    const int tcn  = ((lane >> 4) & 1) * 8;

    float acc[4][4][4];
    #pragma unroll
    for (int i = 0; i < 4; i++)
        #pragma unroll
        for (int j = 0; j < 4; j++)
            #pragma unroll
            for (int r = 0; r < 4; r++) acc[i][j][r] = 0.0f;

    auto issue = [&](int s) {
        const int buf = s % 3;
        const int kb = s * 32;
        CP_ASYNC(saddr(&As[buf][ar][ac]),      Ag + (size_t)ar * 1024 + kb + ac);
        CP_ASYNC(saddr(&As[buf][ar][ac + 16]), Ag + (size_t)ar * 1024 + kb + ac + 16);
        CP_ASYNC(saddr(&Bs[buf][br][bc]),      Bg + (size_t)(kb + br) * NTOT + bc);
        CP_ASYNC(saddr(&Bs[buf][br][bc + 64]), Bg + (size_t)(kb + br) * NTOT + bc + 64);
        CP_COMMIT();
    };

    issue(0);
    issue(1);

    for (int s = 0; s < 32; s++) {
        if (s < 31) { CP_WAIT1(); } else { CP_WAIT0(); }
        __syncthreads();
        if (s + 2 < 32) issue(s + 2);
        const int buf = s % 3;

        #pragma unroll
        for (int ks = 0; ks < 2; ks++) {
            const int k16 = ks * 16;
            uint32_t af[4][4];
            #pragma unroll
            for (int mi = 0; mi < 4; mi++) {
                const uint32_t a = saddr(&As[buf][warp_m * 64 + mi * 16 + lrow][k16 + lch]);
                LDSM_X4(af[mi][0], af[mi][1], af[mi][2], af[mi][3], a);
            }
            uint32_t bf[4][2];
            #pragma unroll
            for (int nn = 0; nn < 2; nn++) {
                const uint32_t a = saddr(&Bs[buf][k16 + trow][warp_n * 32 + nn * 16 + tcn]);
                LDSM_X4_T(bf[2 * nn][0], bf[2 * nn][1], bf[2 * nn + 1][0], bf[2 * nn + 1][1], a);
            }
            #pragma unroll
            for (int mi = 0; mi < 4; mi++)
                #pragma unroll
                for (int ni = 0; ni < 4; ni++)
                    MMA_F16(acc[mi][ni], af[mi], bf[ni]);
        }
    }

    #pragma unroll
    for (int mi = 0; mi < 4; mi++) {
        #pragma unroll
        for (int ni = 0; ni < 4; ni++) {
            const int n = bx * 128 + warp_n * 32 + ni * 8 + 2 * tg;
            const float b0 = bias[n], b1 = bias[n + 1];
            #pragma unroll
            for (int p = 0; p < 2; p++) {
                const int m = by * 128 + warp_m * 64 + mi * 16 + g + p * 8;
                const float vx = acc[mi][ni][2 * p + 0] + b0;
                const float vy = acc[mi][ni][2 * p + 1] + b1;
                if (MODE == 0) {
                    const int b_ = m >> 11;
                    const int t_ = m & 2047;
                    const int sel = n >> 10;
                    const int d = n & 1023;
                    __half* dst = (sel == 0) ? g_qh : ((sel == 1) ? g_kh : g_vh);
                    *(__half2*)&dst[((size_t)(b_ * 16 + (d >> 6)) * 2048 + t_) * 64 + (d & 63)] =
                        __floats2half2_rn(vx, vy);
                } else {
                    float2 v; v.x = vx; v.y = vy;
                    *(float2*)&C[(size_t)m * NTOT + n] = v;
                }
            }
        }
    }
}

// ---------------------------------------------------------------------------
// fp16 flash attention with cp.async double-buffered K/V tiles.
// ---------------------------------------------------------------------------
#define PSTR 72
#define ATTN_SMEM ((4 * 64 * PSTR + 8 * 16 * PSTR) * 2)   // 55296 B

__global__ __launch_bounds__(256, 2)
void attn_tc()
{
    extern __shared__ __half hsm[];
    __half (*Ks)[64][PSTR] = (__half (*)[64][PSTR])hsm;
    __half (*Vs)[64][PSTR] = (__half (*)[64][PSTR])(hsm + 2 * 64 * PSTR);
    __half (*Ps)[16][PSTR] = (__half (*)[16][PSTR])(hsm + 4 * 64 * PSTR);

    const int tid  = threadIdx.x;
    const int lane = tid & 31;
    const int wid  = tid >> 5;
    const int g    = lane >> 2;
    const int tg   = lane & 3;
    const int qt = blockIdx.x;
    const int h  = blockIdx.y;
    const int b  = blockIdx.z;

    const __half* qb = g_qh + (size_t)(b * HH + h) * TT * HD;
    const __half* kb = g_kh + (size_t)(b * HH + h) * TT * HD;
    const __half* vb = g_vh + (size_t)(b * HH + h) * TT * HD;

    __half (*Pw)[PSTR] = Ps[wid];

    // ldmatrix lane-address components
    const int arow = (lane & 7) + ((lane >> 3) & 1) * 8;
    const int ach  = ((lane >> 4) & 1) * 8;
    const int krow = (lane & 7) + ((lane >> 4) & 1) * 8;
    const int kch  = ((lane >> 3) & 1) * 8;
    const int vrow = (lane & 7) + ((lane >> 3) & 1) * 8;
    const int vcn  = ((lane >> 4) & 1) * 8;

    // cp.async staging mapping
    const int sr = tid >> 2;             // 0..63
    const int sc = (tid & 3) << 3;       // 0,8,16,24 (chunks at sc, sc+32)

    auto issueKV = [&](int kt, int buf) {
        const __half* kr = kb + (size_t)(kt * 64 + sr) * 64;
        const __half* vr = vb + (size_t)(kt * 64 + sr) * 64;
        CP_ASYNC(saddr(&Ks[buf][sr][sc]),      kr + sc);
        CP_ASYNC(saddr(&Ks[buf][sr][sc + 32]), kr + sc + 32);
        CP_ASYNC(saddr(&Vs[buf][sr][sc]),      vr + sc);
        CP_ASYNC(saddr(&Vs[buf][sr][sc + 32]), vr + sc + 32);
        CP_COMMIT();
    };

    const int nkt = 2 * qt + 2;
    issueKV(0, 0);

    // ---- load Q fragments into registers (once) ----
    uint32_t Qf[4][4];
    {
        const int r = lane >> 1;
        const int c = (lane & 1) * 32;
        const __half* qrow = qb + (size_t)(qt * 128 + wid * 16 + r) * 64 + c;
        #pragma unroll
        for (int i = 0; i < 4; i++)
            *(uint4*)&Pw[r][c + i * 8] = *(const uint4*)&qrow[i * 8];
        __syncwarp();
        #pragma unroll
        for (int ks = 0; ks < 4; ks++) {
            const uint32_t a = saddr(&Pw[arow][ks * 16 + ach]);
            LDSM_X4(Qf[ks][0], Qf[ks][1], Qf[ks][2], Qf[ks][3], a);
        }
    }

    float O[8][4];
    #pragma unroll
    for (int ni = 0; ni < 8; ni++)
        #pragma unroll
        for (int r = 0; r < 4; r++) O[ni][r] = 0.0f;
    float mi0 = -INFINITY, mi1 = -INFINITY, li0 = 0.0f, li1 = 0.0f;

    const int row0 = qt * 128 + wid * 16 + g;
    const int row1 = row0 + 8;
    const int wrow_min = qt * 128 + wid * 16;
    const float scale = 0.125f;

    for (int kt = 0; kt < nkt; kt++) {
        CP_WAIT0();
        __syncthreads();
        if (kt + 1 < nkt) issueKV(kt + 1, (kt + 1) & 1);
        const int bk = kt & 1;

        // ---- S = Q K^T ----
        float S[8][4];
        #pragma unroll
        for (int ni = 0; ni < 8; ni++)
            #pragma unroll
            for (int r = 0; r < 4; r++) S[ni][r] = 0.0f;

        #pragma unroll
        for (int ks = 0; ks < 4; ks++) {
            uint32_t bf[8][2];
            #pragma unroll
            for (int np = 0; np < 4; np++) {
                const uint32_t a = saddr(&Ks[bk][np * 16 + krow][ks * 16 + kch]);
                LDSM_X4(bf[2 * np][0], bf[2 * np][1], bf[2 * np + 1][0], bf[2 * np + 1][1], a);
            }
            #pragma unroll
            for (int ni = 0; ni < 8; ni++)
                MMA_F16(S[ni], Qf[ks], bf[ni]);
        }

        if (kt * 64 + 63 > wrow_min) {
            #pragma unroll
            for (int ni = 0; ni < 8; ni++) {
                const int c0 = kt * 64 + ni * 8 + 2 * tg;
                S[ni][0] = (c0     > row0) ? -INFINITY : S[ni][0] * scale;
                S[ni][1] = (c0 + 1 > row0) ? -INFINITY : S[ni][1] * scale;
                S[ni][2] = (c0     > row1) ? -INFINITY : S[ni][2] * scale;
                S[ni][3] = (c0 + 1 > row1) ? -INFINITY : S[ni][3] * scale;
            }
        } else {
            #pragma unroll
            for (int ni = 0; ni < 8; ni++) {
                S[ni][0] *= scale; S[ni][1] *= scale;
                S[ni][2] *= scale; S[ni][3] *= scale;
            }
        }

        float m0 = -INFINITY, m1 = -INFINITY;
        #pragma unroll
        for (int ni = 0; ni < 8; ni++) {
            m0 = fmaxf(m0, fmaxf(S[ni][0], S[ni][1]));
            m1 = fmaxf(m1, fmaxf(S[ni][2], S[ni][3]));
        }
        m0 = fmaxf(m0, __shfl_xor_sync(0xffffffffu, m0, 1));
        m0 = fmaxf(m0, __shfl_xor_sync(0xffffffffu, m0, 2));
        m1 = fmaxf(m1, __shfl_xor_sync(0xffffffffu, m1, 1));
        m1 = fmaxf(m1, __shfl_xor_sync(0xffffffffu, m1, 2));
        const float mn0 = fmaxf(mi0, m0);
        const float mn1 = fmaxf(mi1, m1);
        const float a0 = __expf(mi0 - mn0);
        const float a1 = __expf(mi1 - mn1);
        mi0 = mn0; mi1 = mn1;

        float rs0 = 0.0f, rs1 = 0.0f;
        #pragma unroll
        for (int ni = 0; ni < 8; ni++) {
            const float p00 = __expf(S[ni][0] - mn0);
            const float p01 = __expf(S[ni][1] - mn0);
            const float p10 = __expf(S[ni][2] - mn1);
            const float p11 = __expf(S[ni][3] - mn1);
            rs0 += p00 + p01;
            rs1 += p10 + p11;
            *(__half2*)&Pw[g][ni * 8 + 2 * tg]     = __floats2half2_rn(p00, p01);
            *(__half2*)&Pw[g + 8][ni * 8 + 2 * tg] = __floats2half2_rn(p10, p11);
            O[ni][0] *= a0; O[ni][1] *= a0;
            O[ni][2] *= a1; O[ni][3] *= a1;
        }
        rs0 += __shfl_xor_sync(0xffffffffu, rs0, 1);
        rs0 += __shfl_xor_sync(0xffffffffu, rs0, 2);
        rs1 += __shfl_xor_sync(0xffffffffu, rs1, 1);
        rs1 += __shfl_xor_sync(0xffffffffu, rs1, 2);
        li0 = li0 * a0 + rs0;
        li1 = li1 * a1 + rs1;
        __syncwarp();

        // ---- O += P V ----
        #pragma unroll
        for (int ks = 0; ks < 4; ks++) {
            uint32_t af[4];
            {
                const uint32_t a = saddr(&Pw[arow][ks * 16 + ach]);
                LDSM_X4(af[0], af[1], af[2], af[3], a);
            }
            uint32_t bf[8][2];
            #pragma unroll
            for (int np = 0; np < 4; np++) {
                const uint32_t a = saddr(&Vs[bk][ks * 16 + vrow][np * 16 + vcn]);
                LDSM_X4_T(bf[2 * np][0], bf[2 * np][1], bf[2 * np + 1][0], bf[2 * np + 1][1], a);
            }
            #pragma unroll
            for (int ni = 0; ni < 8; ni++)
                MMA_F16(O[ni], af, bf[ni]);
        }
    }

    const float inv0 = 1.0f / li0;
    const float inv1 = 1.0f / li1;
    __half* y0 = g_yh + (size_t)(b * TT + row0) * DD + h * HD;
    __half* y1 = g_yh + (size_t)(b * TT + row1) * DD + h * HD;
    #pragma unroll
    for (int ni = 0; ni < 8; ni++) {
        const int c = ni * 8 + 2 * tg;
        *(__half2*)&y0[c] = __floats2half2_rn(O[ni][0] * inv0, O[ni][1] * inv0);
        *(__half2*)&y1[c] = __floats2half2_rn(O[ni][2] * inv1, O[ni][3] * inv1);
    }
}

// ---------------------------------------------------------------------------
extern "C" void kernel_launch(void* const* d_in, const int* in_sizes, int n_in,
                              void* d_out, int out_size)
{
    (void)in_sizes; (void)n_in; (void)out_size;
    const float* x      = (const float*)d_in[0];
    const float* W_attn = (const float*)d_in[1];
    const float* b_attn = (const float*)d_in[2];
    const float* W_proj = (const float*)d_in[3];
    const float* b_proj = (const float*)d_in[4];
    float* out = (float*)d_out;

    __half *xh = nullptr, *wah = nullptr, *wph = nullptr, *yh = nullptr;
    cudaGetSymbolAddress((void**)&xh, g_xh);
    cudaGetSymbolAddress((void**)&wah, g_wah);
    cudaGetSymbolAddress((void**)&wph, g_wph);
    cudaGetSymbolAddress((void**)&yh, g_yh);

    static bool attr_done = false;
    if (!attr_done) {
        cudaFuncSetAttribute(mma_gemm<0, N3>, cudaFuncAttributeMaxDynamicSharedMemorySize, GEMM_SMEM);
        cudaFuncSetAttribute(mma_gemm<1, DD>, cudaFuncAttributeMaxDynamicSharedMemorySize, GEMM_SMEM);
        cudaFuncSetAttribute(attn_tc, cudaFuncAttributeMaxDynamicSharedMemorySize, ATTN_SMEM);
        attr_done = true;
    }

    // 0) convert inputs to fp16 (RNE)
    f2h<<<592, 256>>>((const float4*)x, (__half2*)xh, MM * DD / 4);
    f2h<<<592, 256>>>((const float4*)W_attn, (__half2*)wah, DD * N3 / 4);
    f2h<<<592, 256>>>((const float4*)W_proj, (__half2*)wph, DD * DD / 4);

    // 1) QKV projection + head-layout scatter (fp16 out)
    mma_gemm<0, N3><<<dim3(N3 / 128, MM / 128), 256, GEMM_SMEM>>>(xh, wah, b_attn, nullptr);

    // 2) causal flash attention (fp16 mma, fp32 softmax)
    attn_tc<<<dim3(TT / 128, HH, BB), 256, ATTN_SMEM>>>();

    // 3) output projection (fp32 out)
    mma_gemm<1, DD><<<dim3(DD / 128, MM / 128), 256, GEMM_SMEM>>>(yh, wph, b_proj, out);
}